// round 2
// baseline (speedup 1.0000x reference)
#include <cuda_runtime.h>
#include <math.h>

// Problem constants (shapes are fixed by the dataset)
#define D     128
#define NMAX  32768
#define KPAD  10112   // 79 tiles * 128

// -------- scratch (static device memory: allowed; runtime alloc is not) ----
__device__ float g_halfnorm[KPAD];
__device__ int   g_bestidx[NMAX];
__device__ float g_counts[KPAD];          // counts, then new_size
__device__ float g_sums[KPAD * D];        // scattered sums
__device__ float g_newmean[KPAD * D];
__device__ float g_scalars[2];            // [0]=n_sample, [1]=loss sum

// -------- helpers -----------------------------------------------------------
__device__ __forceinline__ unsigned long long ffma2(unsigned long long a,
                                                    unsigned long long b,
                                                    unsigned long long c) {
    unsigned long long d_;
    asm("fma.rn.f32x2 %0, %1, %2, %3;" : "=l"(d_) : "l"(a), "l"(b), "l"(c));
    return d_;
}
__device__ __forceinline__ unsigned long long pack2(float a) {
    unsigned long long u;
    asm("mov.b64 %0, {%1, %1};" : "=l"(u) : "f"(a));
    return u;
}
__device__ __forceinline__ void unpack2(unsigned long long u, float& x, float& y) {
    asm("mov.b64 {%0, %1}, %2;" : "=f"(x), "=f"(y) : "l"(u));
}

__device__ __forceinline__ float blockReduceSum(float v) {
    __shared__ float sh[32];
    int lane = threadIdx.x & 31, wid = threadIdx.x >> 5;
    #pragma unroll
    for (int o = 16; o > 0; o >>= 1) v += __shfl_down_sync(0xffffffffu, v, o);
    if (lane == 0) sh[wid] = v;
    __syncthreads();
    int nw = (blockDim.x + 31) >> 5;
    v = (wid == 0 && lane < nw) ? sh[lane] : 0.0f;
    if (wid == 0) {
        #pragma unroll
        for (int o = 16; o > 0; o >>= 1) v += __shfl_down_sync(0xffffffffu, v, o);
    }
    return v;  // valid in thread 0
}

// -------- kernel 0: zero scratch --------------------------------------------
__global__ void zero_kernel() {
    int i = blockIdx.x * blockDim.x + threadIdx.x;
    if (i < KPAD) g_counts[i] = 0.0f;
    if (i < 2)    g_scalars[i] = 0.0f;
    int stride = gridDim.x * blockDim.x;
    for (int e = i; e < KPAD * D; e += stride) g_sums[e] = 0.0f;
}

// -------- kernel 1: half-norms of centroids ---------------------------------
__global__ void halfnorm_kernel(const float* __restrict__ E, int K, int Kpad) {
    int w    = (blockIdx.x * blockDim.x + threadIdx.x) >> 5;
    int lane = threadIdx.x & 31;
    if (w >= Kpad) return;
    if (w >= K) { if (lane == 0) g_halfnorm[w] = INFINITY; return; }
    const float4* row = (const float4*)(E + (size_t)w * D);
    float4 v = row[lane];                       // 32 lanes * 4 = 128
    float s = v.x * v.x + v.y * v.y + v.z * v.z + v.w * v.w;
    #pragma unroll
    for (int o = 16; o > 0; o >>= 1) s += __shfl_down_sync(0xffffffffu, s, o);
    if (lane == 0) g_halfnorm[w] = 0.5f * s;
}

// -------- kernel 2: nearest-centroid GEMM + argmin --------------------------
// Block: 256 threads (16x16). BM=128 samples (A resident in smem for all D),
// BN=128 centroids per tile, double-buffered KC=16 chunks, 8x8 micro-tile,
// accumulators as packed f32x2.
__global__ __launch_bounds__(256)
void argmin_kernel(const float* __restrict__ X, const float* __restrict__ E,
                   int K, int numTiles) {
    extern __shared__ float smem[];
    float* As = smem;                    // [128][128] transposed: As[d][m]
    float* Bs = smem + D * 128;          // [2][16][128]
    float* Hs = Bs + 2 * 16 * 128;       // [128]

    const int tid = threadIdx.x;
    const int tx = tid & 15, ty = tid >> 4;
    const int rowbase = blockIdx.x * 128;

    // Load A tile transposed (coalesced float4 reads)
    #pragma unroll
    for (int i = 0; i < 16; i++) {
        int f  = tid + i * 256;          // 0..4095
        int m  = f >> 5;
        int d4 = f & 31;
        float4 v = *(const float4*)(X + (size_t)(rowbase + m) * D + d4 * 4);
        As[(d4 * 4 + 0) * 128 + m] = v.x;
        As[(d4 * 4 + 1) * 128 + m] = v.y;
        As[(d4 * 4 + 2) * 128 + m] = v.z;
        As[(d4 * 4 + 3) * 128 + m] = v.w;
    }

    const int jj0 = tid >> 2;            // 0..63  (smem column for first B row)
    const int jj1 = jj0 + 64;            // 64..127 (smem column for second B row)
    const int d40 = tid & 3;             // which 4-float group of the 16-wide chunk
    const int C = numTiles * 8;

    // prologue: load chunk 0 into buf 0, load Hs for jt=0
    {
        int j0 = jj0, j1 = jj1;
        int col = d40 * 4;
        float4 ra = (j0 < K) ? *(const float4*)(E + (size_t)j0 * D + col)
                             : make_float4(0.f, 0.f, 0.f, 0.f);
        float4 rb = (j1 < K) ? *(const float4*)(E + (size_t)j1 * D + col)
                             : make_float4(0.f, 0.f, 0.f, 0.f);
        float* b = Bs;
        b[(d40 * 4 + 0) * 128 + jj0] = ra.x; b[(d40 * 4 + 1) * 128 + jj0] = ra.y;
        b[(d40 * 4 + 2) * 128 + jj0] = ra.z; b[(d40 * 4 + 3) * 128 + jj0] = ra.w;
        b[(d40 * 4 + 0) * 128 + jj1] = rb.x; b[(d40 * 4 + 1) * 128 + jj1] = rb.y;
        b[(d40 * 4 + 2) * 128 + jj1] = rb.z; b[(d40 * 4 + 3) * 128 + jj1] = rb.w;
        if (tid < 128) Hs[tid] = g_halfnorm[tid];
    }
    __syncthreads();

    unsigned long long acc[8][4];
    float best[8]; int bidx[8];
    #pragma unroll
    for (int r = 0; r < 8; r++) { best[r] = -INFINITY; bidx[r] = 0; }

    for (int c = 0; c < C; ++c) {
        const int jt = c >> 3, kc = c & 7, buf = c & 1;

        // issue global loads for chunk c+1 (latency hidden by compute)
        float4 ra, rb; bool have_next = (c + 1 < C);
        if (have_next) {
            int jt2 = (c + 1) >> 3, kc2 = (c + 1) & 7;
            int j0 = jt2 * 128 + jj0, j1 = jt2 * 128 + jj1;
            int col = kc2 * 16 + d40 * 4;
            ra = (j0 < K) ? *(const float4*)(E + (size_t)j0 * D + col)
                          : make_float4(0.f, 0.f, 0.f, 0.f);
            rb = (j1 < K) ? *(const float4*)(E + (size_t)j1 * D + col)
                          : make_float4(0.f, 0.f, 0.f, 0.f);
        }

        if (kc == 0) {
            #pragma unroll
            for (int r = 0; r < 8; r++)
                #pragma unroll
                for (int p = 0; p < 4; p++) acc[r][p] = 0ull;
        }

        // compute 16 k-steps from Bs[buf]
        const float* bbase = Bs + buf * 2048;
        #pragma unroll
        for (int kk = 0; kk < 16; ++kk) {
            const float* arow = &As[(kc * 16 + kk) * 128 + ty * 8];
            float4 a0 = *(const float4*)arow;
            float4 a1 = *(const float4*)(arow + 4);
            const ulonglong2* bp = (const ulonglong2*)(bbase + kk * 128 + tx * 8);
            ulonglong2 b01 = bp[0], b23 = bp[1];
            float a[8] = {a0.x, a0.y, a0.z, a0.w, a1.x, a1.y, a1.z, a1.w};
            #pragma unroll
            for (int r = 0; r < 8; ++r) {
                unsigned long long ap = pack2(a[r]);
                acc[r][0] = ffma2(ap, b01.x, acc[r][0]);
                acc[r][1] = ffma2(ap, b01.y, acc[r][1]);
                acc[r][2] = ffma2(ap, b23.x, acc[r][2]);
                acc[r][3] = ffma2(ap, b23.y, acc[r][3]);
            }
        }

        if (kc == 7) {  // epilogue: score = x·e - 0.5||e||^2 ; argmax == argmin dist
            int jb = jt * 128 + tx * 8;
            #pragma unroll
            for (int r = 0; r < 8; ++r) {
                #pragma unroll
                for (int p = 0; p < 4; ++p) {
                    float s0, s1; unpack2(acc[r][p], s0, s1);
                    s0 -= Hs[tx * 8 + p * 2];
                    s1 -= Hs[tx * 8 + p * 2 + 1];
                    if (s0 > best[r]) { best[r] = s0; bidx[r] = jb + p * 2; }
                    if (s1 > best[r]) { best[r] = s1; bidx[r] = jb + p * 2 + 1; }
                }
            }
        }

        __syncthreads();
        if (have_next) {
            float* b = Bs + ((c + 1) & 1) * 2048;
            b[(d40 * 4 + 0) * 128 + jj0] = ra.x; b[(d40 * 4 + 1) * 128 + jj0] = ra.y;
            b[(d40 * 4 + 2) * 128 + jj0] = ra.z; b[(d40 * 4 + 3) * 128 + jj0] = ra.w;
            b[(d40 * 4 + 0) * 128 + jj1] = rb.x; b[(d40 * 4 + 1) * 128 + jj1] = rb.y;
            b[(d40 * 4 + 2) * 128 + jj1] = rb.z; b[(d40 * 4 + 3) * 128 + jj1] = rb.w;
            if (((c + 1) & 7) == 0 && tid < 128)
                Hs[tid] = g_halfnorm[(jt + 1) * 128 + tid];
        }
        __syncthreads();
    }

    // cross-thread reduction (16 tx per sample row) in smem (reuse As)
    float* sv = As;                 // [128][16]
    int*   si = (int*)(As + 2048);  // [128][16]
    #pragma unroll
    for (int r = 0; r < 8; r++) {
        int row = ty * 8 + r;
        sv[row * 16 + tx] = best[r];
        si[row * 16 + tx] = bidx[r];
    }
    __syncthreads();
    if (tid < 128) {
        float b = sv[tid * 16]; int bj = si[tid * 16];
        #pragma unroll
        for (int t = 1; t < 16; t++) {
            float v = sv[tid * 16 + t]; int j = si[tid * 16 + t];
            if (v > b || (v == b && j < bj)) { b = v; bj = j; }
        }
        g_bestidx[rowbase + tid] = bj;
    }
}

// -------- kernel 3: scatter counts & sums (one warp per sample) -------------
__global__ void scatter_kernel(const float* __restrict__ X, int N) {
    int w    = (blockIdx.x * blockDim.x + threadIdx.x) >> 5;
    int lane = threadIdx.x & 31;
    if (w >= N) return;
    int j = g_bestidx[w];
    float4 v = ((const float4*)(X + (size_t)w * D))[lane];
    float* dst = &g_sums[(size_t)j * D + lane * 4];
    atomicAdd(dst + 0, v.x); atomicAdd(dst + 1, v.y);
    atomicAdd(dst + 2, v.z); atomicAdd(dst + 3, v.w);
    if (lane == 0) atomicAdd(&g_counts[j], 1.0f);
}

// -------- kernel 4: new_size + n_sample --------------------------------------
__global__ void size_kernel(const float* __restrict__ csize, int K) {
    int j = blockIdx.x * blockDim.x + threadIdx.x;
    float ns = 0.0f;
    if (j < K) {
        ns = csize[j] * 0.99f + g_counts[j] * 0.01f;
        g_counts[j] = ns;   // now holds new_size
    }
    float tot = blockReduceSum(ns);
    if (threadIdx.x == 0) atomicAdd(&g_scalars[0], tot);
}

// -------- kernel 5: new_mean --------------------------------------------------
__global__ void mean_kernel(const float* __restrict__ csum, int K) {
    int e = blockIdx.x * blockDim.x + threadIdx.x;
    if (e >= K * D) return;
    int j = e >> 7;
    float nsamp = g_scalars[0];
    float smoothed = (g_counts[j] + 1e-5f) * nsamp / (nsamp + (float)K * 1e-5f);
    g_newmean[e] = (csum[e] * 0.99f + g_sums[e] * 0.01f) / smoothed;
}

// -------- kernel 6: gather + loss --------------------------------------------
__global__ void gather_kernel(const float* __restrict__ X, float* __restrict__ out,
                              int N) {
    int e = blockIdx.x * blockDim.x + threadIdx.x;   // one per element of N*D
    int i = e >> 7, d = e & 127;
    int j = g_bestidx[i];
    float q = g_newmean[(size_t)j * D + d];
    float x = X[e];
    out[e] = x + (q - x);          // matches reference rounding exactly
    float df = x - q;
    float tot = blockReduceSum(df * df);
    if (threadIdx.x == 0) atomicAdd(&g_scalars[1], tot);
}

// -------- kernel 7: idx + loss outputs ----------------------------------------
__global__ void final_kernel(float* __restrict__ out, int N, long long out_size) {
    int i = blockIdx.x * blockDim.x + threadIdx.x;
    long long base = (long long)N * D;
    if (i < N && base + i < out_size) out[base + i] = (float)g_bestidx[i];
    if (i == 0 && base + N < out_size)
        out[base + N] = 0.25f * g_scalars[1] / (float)((long long)N * D);
}

// -------- launch ---------------------------------------------------------------
extern "C" void kernel_launch(void* const* d_in, const int* in_sizes, int n_in,
                              void* d_out, int out_size) {
    const float* X     = (const float*)d_in[0];   // inputs  [N, 128]
    const float* E     = (const float*)d_in[1];   // cluster_mean [K, 128]
    const float* csize = (const float*)d_in[2];   // cluster_size [K]
    const float* csum  = (const float*)d_in[3];   // cluster_sum  [K, 128]
    float* out = (float*)d_out;

    int K = in_sizes[2];
    int N = in_sizes[0] / D;
    int numTiles = (K + 127) / 128;
    if (numTiles * 128 > KPAD) numTiles = KPAD / 128;
    int Kpad = numTiles * 128;

    size_t smemBytes = (size_t)(D * 128 + 2 * 16 * 128 + 128) * sizeof(float); // 82432
    cudaFuncSetAttribute(argmin_kernel,
                         cudaFuncAttributeMaxDynamicSharedMemorySize,
                         (int)smemBytes);

    zero_kernel<<<(KPAD * D + 255) / 256, 256>>>();
    halfnorm_kernel<<<(Kpad * 32 + 255) / 256, 256>>>(E, K, Kpad);
    argmin_kernel<<<N / 128, 256, smemBytes>>>(X, E, K, numTiles);
    scatter_kernel<<<(N * 32 + 255) / 256, 256>>>(X, N);
    size_kernel<<<(K + 255) / 256, 256>>>(csize, K);
    mean_kernel<<<(K * D + 255) / 256, 256>>>(csum, K);
    gather_kernel<<<(N * D) / 256, 256>>>(X, out, N);
    final_kernel<<<(N + 255) / 256, 256>>>(out, N, (long long)out_size);
}

// round 4
// speedup vs baseline: 1.7815x; 1.7815x over previous
#include <cuda_runtime.h>
#include <cstdint>
#include <math.h>

#define D       128
#define NMAX    32768
#define KPAD    10112                 // 158 tiles * 64
#define NTILE   (KPAD / 64)           // 158
#define NSEG    4

// ---------------- scratch ----------------------------------------------------
__device__ float g_halfnorm[KPAD];
__device__ unsigned long long g_best[NMAX];
__device__ int   g_bestidx[NMAX];
__device__ float g_counts[KPAD];
__device__ float g_sums[KPAD * D];
__device__ float g_newmean[KPAD * D];
__device__ float g_scalars[2];

// fragment-ordered prepped operands
__device__ __align__(16) float4 g_af4[(NMAX / 16) * 16 * 32];     // 16 MB
__device__ __align__(16) float2 g_bh2[(KPAD / 8) * 16 * 32];      // 5.2 MB
__device__ __align__(16) float2 g_bl2[(KPAD / 8) * 16 * 32];      // 5.2 MB

// ---------------- helpers ----------------------------------------------------
__device__ __forceinline__ float tf32_rna(float x) {
    uint32_t u;
    asm("cvt.rna.tf32.f32 %0, %1;" : "=r"(u) : "f"(x));
    return __uint_as_float(u);
}
__device__ __forceinline__ uint32_t smem_to_u32(const void* p) {
    uint32_t a;
    asm("{ .reg .u64 t; cvta.to.shared.u64 t, %1; cvt.u32.u64 %0, t; }"
        : "=r"(a) : "l"(p));
    return a;
}
__device__ __forceinline__ unsigned long long cvta_g(const void* p) {
    unsigned long long r;
    asm("cvta.to.global.u64 %0, %1;" : "=l"(r) : "l"(p));
    return r;
}
__device__ __forceinline__ void cp_async16(uint32_t dst, const void* src) {
    asm volatile("cp.async.cg.shared.global [%0], [%1], 16;"
                 :: "r"(dst), "l"(cvta_g(src)) : "memory");
}
#define CP_COMMIT() asm volatile("cp.async.commit_group;" ::: "memory")
#define CP_WAIT1()  asm volatile("cp.async.wait_group 1;" ::: "memory")

#define MMA(d, a, b0, b1) \
    asm volatile("mma.sync.aligned.m16n8k8.row.col.f32.tf32.tf32.f32 " \
        "{%0,%1,%2,%3},{%4,%5,%6,%7},{%8,%9},{%0,%1,%2,%3};" \
        : "+f"((d)[0]), "+f"((d)[1]), "+f"((d)[2]), "+f"((d)[3]) \
        : "r"((a)[0]), "r"((a)[1]), "r"((a)[2]), "r"((a)[3]), \
          "r"(b0), "r"(b1))

__device__ __forceinline__ unsigned long long pack_cand(float s, int j) {
    uint32_t u = __float_as_uint(s);
    u = (u & 0x80000000u) ? ~u : (u | 0x80000000u);
    return ((unsigned long long)u << 32) | (uint32_t)(~j);
}

__device__ __forceinline__ float blockReduceSum(float v) {
    __shared__ float sh[32];
    int lane = threadIdx.x & 31, wid = threadIdx.x >> 5;
    #pragma unroll
    for (int o = 16; o > 0; o >>= 1) v += __shfl_down_sync(0xffffffffu, v, o);
    if (lane == 0) sh[wid] = v;
    __syncthreads();
    int nw = (blockDim.x + 31) >> 5;
    v = (wid == 0 && lane < nw) ? sh[lane] : 0.0f;
    if (wid == 0) {
        #pragma unroll
        for (int o = 16; o > 0; o >>= 1) v += __shfl_down_sync(0xffffffffu, v, o);
    }
    return v;
}

// ---------------- prep kernels -----------------------------------------------
__global__ void zero_kernel() {
    int i = blockIdx.x * blockDim.x + threadIdx.x;
    if (i < KPAD) g_counts[i] = 0.0f;
    if (i < 2)    g_scalars[i] = 0.0f;
    if (i < NMAX) g_best[i] = 0ull;
    int stride = gridDim.x * blockDim.x;
    for (int e = i; e < KPAD * D; e += stride) g_sums[e] = 0.0f;
}
__global__ void halfnorm_kernel(const float* __restrict__ E, int K) {
    int w    = (blockIdx.x * blockDim.x + threadIdx.x) >> 5;
    int lane = threadIdx.x & 31;
    if (w >= KPAD) return;
    if (w >= K) { if (lane == 0) g_halfnorm[w] = INFINITY; return; }
    const float4* row = (const float4*)(E + (size_t)w * D);
    float4 v = row[lane];
    float s = v.x * v.x + v.y * v.y + v.z * v.z + v.w * v.w;
    #pragma unroll
    for (int o = 16; o > 0; o >>= 1) s += __shfl_down_sync(0xffffffffu, s, o);
    if (lane == 0) g_halfnorm[w] = 0.5f * s;
}
// A -> fragment order: g_af4[(mg*16+kc)*32+lane] = {a0,a1,a2,a3}
__global__ void prep_a(const float* __restrict__ X) {
    int t = blockIdx.x * blockDim.x + threadIdx.x;
    if (t >= (NMAX / 16) * 512) return;
    int lane = t & 31, kc = (t >> 5) & 15, mg = t >> 9;
    int r0 = mg * 16 + (lane >> 2);
    int c0 = kc * 8 + (lane & 3);
    float4 v;
    v.x = X[(size_t)r0 * D + c0];
    v.y = X[(size_t)(r0 + 8) * D + c0];
    v.z = X[(size_t)r0 * D + c0 + 4];
    v.w = X[(size_t)(r0 + 8) * D + c0 + 4];
    g_af4[t] = v;
}
// B -> tf32 hi/lo fragment order: g_b*2[(ng*16+kc)*32+lane] = {b0,b1}
__global__ void prep_b(const float* __restrict__ E, int K) {
    int t = blockIdx.x * blockDim.x + threadIdx.x;
    if (t >= (KPAD / 8) * 512) return;
    int lane = t & 31, kc = (t >> 5) & 15, ng = t >> 9;
    int j = ng * 8 + (lane >> 2);
    int k0 = kc * 8 + (lane & 3);
    float e0 = (j < K) ? E[(size_t)j * D + k0]     : 0.0f;
    float e1 = (j < K) ? E[(size_t)j * D + k0 + 4] : 0.0f;
    float2 bh, bl;
    bh.x = tf32_rna(e0); bl.x = tf32_rna(e0 - bh.x);
    bh.y = tf32_rna(e1); bl.y = tf32_rna(e1 - bh.y);
    g_bh2[t] = bh;
    g_bl2[t] = bl;
}

// ---------------- argmin GEMM (mma.sync tf32, 3-pass) ------------------------
// smem: As(raw fp32 A frags, 64KB) | B[2 buf][hi,lo] 128KB | Hs[2][64] 512B
#define OFF_B   65536
#define OFF_HS  196608
#define SMEM_SZ 197120

__device__ __forceinline__ void issue_tile(uint32_t sb, int buf, int t, int tid) {
    const float2* srcH = g_bh2 + (size_t)t * 4096;   // 8 ng * 512 float2
    const float2* srcL = g_bl2 + (size_t)t * 4096;
    uint32_t dH = sb + OFF_B + buf * 65536;
    uint32_t dL = dH + 32768;
    #pragma unroll
    for (int i = 0; i < 8; i++) {
        int idx = tid + i * 256;
        cp_async16(dH + idx * 16, srcH + idx * 2);
        cp_async16(dL + idx * 16, srcL + idx * 2);
    }
    if (tid < 16)
        cp_async16(sb + OFF_HS + buf * 256 + tid * 16, g_halfnorm + t * 64 + tid * 4);
}

__global__ __launch_bounds__(256, 1)
void argmin_mma(int K) {
    extern __shared__ char smem[];
    uint32_t sb = smem_to_u32(smem);
    const int tid   = threadIdx.x;
    const int lane  = tid & 31, wid = tid >> 5;
    const int mwarp = wid >> 1, nwarp = wid & 1;     // 4 x 2
    const int rt  = blockIdx.x >> 2;
    const int seg = blockIdx.x & 3;
    const int tb = (seg * NTILE) / NSEG;
    const int te = ((seg + 1) * NTILE) / NSEG;

    // prologue: A tile + first two B tiles via cp.async
    {
        const float4* srcA = g_af4 + (size_t)rt * 8 * 512;
        #pragma unroll
        for (int i = 0; i < 16; i++) {
            int idx = tid + i * 256;
            cp_async16(sb + idx * 16, srcA + idx);
        }
        issue_tile(sb, 0, tb, tid);
        CP_COMMIT();                        // G0: A + tile tb
        if (tb + 1 < te) issue_tile(sb, 1, tb + 1, tid);
        CP_COMMIT();                        // G1
        CP_WAIT1();                         // G0 done
        __syncthreads();
    }

    const float4* As4 = (const float4*)smem;

    float best[4]; int bidx[4];
    #pragma unroll
    for (int r = 0; r < 4; r++) { best[r] = -INFINITY; bidx[r] = 0; }

    for (int t = tb; t < te; t++) {
        const int buf = (t - tb) & 1;
        const float2* Bh2 = (const float2*)(smem + OFF_B + buf * 65536);
        const float2* Bl2 = (const float2*)(smem + OFF_B + buf * 65536 + 32768);

        float acc[2][4][4];
        #pragma unroll
        for (int mf = 0; mf < 2; mf++)
            #pragma unroll
            for (int nf = 0; nf < 4; nf++)
                #pragma unroll
                for (int e = 0; e < 4; e++) acc[mf][nf][e] = 0.0f;

        #pragma unroll
        for (int kc = 0; kc < 16; kc++) {
            uint32_t ah[2][4], al[2][4];
            #pragma unroll
            for (int mf = 0; mf < 2; mf++) {
                float4 x = As4[((mwarp * 2 + mf) * 16 + kc) * 32 + lane];
                float h;
                h = tf32_rna(x.x); ah[mf][0] = __float_as_uint(h);
                al[mf][0] = __float_as_uint(tf32_rna(x.x - h));
                h = tf32_rna(x.y); ah[mf][1] = __float_as_uint(h);
                al[mf][1] = __float_as_uint(tf32_rna(x.y - h));
                h = tf32_rna(x.z); ah[mf][2] = __float_as_uint(h);
                al[mf][2] = __float_as_uint(tf32_rna(x.z - h));
                h = tf32_rna(x.w); ah[mf][3] = __float_as_uint(h);
                al[mf][3] = __float_as_uint(tf32_rna(x.w - h));
            }
            uint32_t bh[4][2], bl[4][2];
            #pragma unroll
            for (int nf = 0; nf < 4; nf++) {
                float2 vh = Bh2[((nwarp * 4 + nf) * 16 + kc) * 32 + lane];
                float2 vl = Bl2[((nwarp * 4 + nf) * 16 + kc) * 32 + lane];
                bh[nf][0] = __float_as_uint(vh.x); bh[nf][1] = __float_as_uint(vh.y);
                bl[nf][0] = __float_as_uint(vl.x); bl[nf][1] = __float_as_uint(vl.y);
            }
            #pragma unroll
            for (int mf = 0; mf < 2; mf++)
                #pragma unroll
                for (int nf = 0; nf < 4; nf++) {
                    MMA(acc[mf][nf], ah[mf], bh[nf][0], bh[nf][1]);
                    MMA(acc[mf][nf], ah[mf], bl[nf][0], bl[nf][1]);
                    MMA(acc[mf][nf], al[mf], bh[nf][0], bh[nf][1]);
                }
        }

        // epilogue: score = dot - halfnorm; running argmax (j ascending -> strict >)
        const float* Hsf = (const float*)(smem + OFF_HS + buf * 256);
        const int cb = nwarp * 32 + (lane & 3) * 2;
        #pragma unroll
        for (int mf = 0; mf < 2; mf++)
            #pragma unroll
            for (int nf = 0; nf < 4; nf++) {
                int cl = cb + nf * 8;
                float hn0 = Hsf[cl], hn1 = Hsf[cl + 1];
                int j0 = t * 64 + cl;
                float s0 = acc[mf][nf][0] - hn0;
                float s1 = acc[mf][nf][1] - hn1;
                float s2 = acc[mf][nf][2] - hn0;
                float s3 = acc[mf][nf][3] - hn1;
                int r0 = mf * 2, r1 = mf * 2 + 1;
                if (s0 > best[r0]) { best[r0] = s0; bidx[r0] = j0; }
                if (s1 > best[r0]) { best[r0] = s1; bidx[r0] = j0 + 1; }
                if (s2 > best[r1]) { best[r1] = s2; bidx[r1] = j0; }
                if (s3 > best[r1]) { best[r1] = s3; bidx[r1] = j0 + 1; }
            }

        __syncthreads();                       // everyone done reading buf
        if (t + 2 < te) issue_tile(sb, buf, t + 2, tid);
        CP_COMMIT();                           // (possibly empty) group
        CP_WAIT1();                            // tile t+1 resident
        __syncthreads();
    }

    // merge into global packed (score, ~idx) via atomicMax
    #pragma unroll
    for (int rs = 0; rs < 4; rs++) {
        int mf = rs >> 1, rh = rs & 1;
        int row = rt * 128 + mwarp * 32 + mf * 16 + (lane >> 2) + rh * 8;
        atomicMax(&g_best[row], pack_cand(best[rs], bidx[rs]));
    }
}

__global__ void decode_kernel(int N) {
    int i = blockIdx.x * blockDim.x + threadIdx.x;
    if (i < N) g_bestidx[i] = (int)(~(unsigned int)(g_best[i] & 0xffffffffull));
}

// ---------------- tail kernels (unchanged, known-correct) --------------------
__global__ void scatter_kernel(const float* __restrict__ X, int N) {
    int w    = (blockIdx.x * blockDim.x + threadIdx.x) >> 5;
    int lane = threadIdx.x & 31;
    if (w >= N) return;
    int j = g_bestidx[w];
    float4 v = ((const float4*)(X + (size_t)w * D))[lane];
    float* dst = &g_sums[(size_t)j * D + lane * 4];
    atomicAdd(dst + 0, v.x); atomicAdd(dst + 1, v.y);
    atomicAdd(dst + 2, v.z); atomicAdd(dst + 3, v.w);
    if (lane == 0) atomicAdd(&g_counts[j], 1.0f);
}
__global__ void size_kernel(const float* __restrict__ csize, int K) {
    int j = blockIdx.x * blockDim.x + threadIdx.x;
    float ns = 0.0f;
    if (j < K) {
        ns = csize[j] * 0.99f + g_counts[j] * 0.01f;
        g_counts[j] = ns;
    }
    float tot = blockReduceSum(ns);
    if (threadIdx.x == 0) atomicAdd(&g_scalars[0], tot);
}
__global__ void mean_kernel(const float* __restrict__ csum, int K) {
    int e = blockIdx.x * blockDim.x + threadIdx.x;
    if (e >= K * D) return;
    int j = e >> 7;
    float nsamp = g_scalars[0];
    float smoothed = (g_counts[j] + 1e-5f) * nsamp / (nsamp + (float)K * 1e-5f);
    g_newmean[e] = (csum[e] * 0.99f + g_sums[e] * 0.01f) / smoothed;
}
__global__ void gather_kernel(const float* __restrict__ X, float* __restrict__ out,
                              int N) {
    int e = blockIdx.x * blockDim.x + threadIdx.x;
    int i = e >> 7, d = e & 127;
    int j = g_bestidx[i];
    float q = g_newmean[(size_t)j * D + d];
    float x = X[e];
    out[e] = x + (q - x);
    float df = x - q;
    float tot = blockReduceSum(df * df);
    if (threadIdx.x == 0) atomicAdd(&g_scalars[1], tot);
}
__global__ void final_kernel(float* __restrict__ out, int N, long long out_size) {
    int i = blockIdx.x * blockDim.x + threadIdx.x;
    long long base = (long long)N * D;
    if (i < N && base + i < out_size) out[base + i] = (float)g_bestidx[i];
    if (i == 0 && base + N < out_size)
        out[base + N] = 0.25f * g_scalars[1] / (float)((long long)N * D);
}

// ---------------- launch ------------------------------------------------------
extern "C" void kernel_launch(void* const* d_in, const int* in_sizes, int n_in,
                              void* d_out, int out_size) {
    const float* X     = (const float*)d_in[0];
    const float* E     = (const float*)d_in[1];
    const float* csize = (const float*)d_in[2];
    const float* csum  = (const float*)d_in[3];
    float* out = (float*)d_out;

    int K = in_sizes[2];
    int N = in_sizes[0] / D;

    cudaFuncSetAttribute(argmin_mma, cudaFuncAttributeMaxDynamicSharedMemorySize,
                         SMEM_SZ);

    zero_kernel<<<(KPAD * D + 255) / 256, 256>>>();
    halfnorm_kernel<<<(KPAD * 32 + 255) / 256, 256>>>(E, K);
    prep_a<<<((NMAX / 16) * 512 + 255) / 256, 256>>>(X);
    prep_b<<<((KPAD / 8) * 512 + 255) / 256, 256>>>(E, K);
    argmin_mma<<<(N / 128) * NSEG, 256, SMEM_SZ>>>(K);
    decode_kernel<<<(N + 255) / 256, 256>>>(N);
    scatter_kernel<<<(N * 32 + 255) / 256, 256>>>(X, N);
    size_kernel<<<(K + 255) / 256, 256>>>(csize, K);
    mean_kernel<<<(K * D + 255) / 256, 256>>>(csum, K);
    gather_kernel<<<(N * D) / 256, 256>>>(X, out, N);
    final_kernel<<<(N + 255) / 256, 256>>>(out, N, (long long)out_size);
}

// round 5
// speedup vs baseline: 3.4129x; 1.9158x over previous
#include <cuda_runtime.h>
#include <cuda_fp16.h>
#include <cstdint>
#include <math.h>

#define D       128
#define NMAX    32768
#define KPAD    10112                 // 158 tiles * 64
#define NTILE   (KPAD / 64)           // 158
#define NSEG    4
#define LO_SCALE   4096.0f
#define LO_INV     (1.0f / 4096.0f)

// ---------------- scratch ----------------------------------------------------
__device__ float g_halfnorm[KPAD];
__device__ unsigned long long g_best[NMAX];
__device__ int   g_bestidx[NMAX];
__device__ float g_counts[KPAD];
__device__ float g_sums[KPAD * D];
__device__ float g_newmean[KPAD * D];
__device__ float g_scalars[2];

// fragment-ordered fp16 operands
// A: per 16-row group mg (0..2047), kc (0..7), lane: uint4 = 4 half2 regs
__device__ __align__(16) uint4 g_ah4[(NMAX / 16) * 8 * 32];   // 8 MB
__device__ __align__(16) uint4 g_al4[(NMAX / 16) * 8 * 32];   // 8 MB
// B: per 8-col group ng (0..1263), kc (0..7), lane: uint4 = {h0,h1,l0,l1}
__device__ __align__(16) uint4 g_bf4[(KPAD / 8) * 8 * 32];    // 5.2 MB

// ---------------- helpers ----------------------------------------------------
__device__ __forceinline__ uint32_t smem_to_u32(const void* p) {
    uint32_t a;
    asm("{ .reg .u64 t; cvta.to.shared.u64 t, %1; cvt.u32.u64 %0, t; }"
        : "=r"(a) : "l"(p));
    return a;
}
__device__ __forceinline__ unsigned long long cvta_g(const void* p) {
    unsigned long long r;
    asm("cvta.to.global.u64 %0, %1;" : "=l"(r) : "l"(p));
    return r;
}
__device__ __forceinline__ void cp_async16(uint32_t dst, const void* src) {
    asm volatile("cp.async.cg.shared.global [%0], [%1], 16;"
                 :: "r"(dst), "l"(cvta_g(src)) : "memory");
}
#define CP_COMMIT() asm volatile("cp.async.commit_group;" ::: "memory")
#define CP_WAIT1()  asm volatile("cp.async.wait_group 1;" ::: "memory")

#define MMA16(d, a, b0, b1) \
    asm volatile("mma.sync.aligned.m16n8k16.row.col.f32.f16.f16.f32 " \
        "{%0,%1,%2,%3},{%4,%5,%6,%7},{%8,%9},{%0,%1,%2,%3};" \
        : "+f"((d)[0]), "+f"((d)[1]), "+f"((d)[2]), "+f"((d)[3]) \
        : "r"((a).x), "r"((a).y), "r"((a).z), "r"((a).w), \
          "r"(b0), "r"(b1))

__device__ __forceinline__ unsigned long long pack_cand(float s, int j) {
    uint32_t u = __float_as_uint(s);
    u = (u & 0x80000000u) ? ~u : (u | 0x80000000u);
    return ((unsigned long long)u << 32) | (uint32_t)(~j);
}
__device__ __forceinline__ uint32_t h2pack(float a, float b) {
    __half2 h = __halves2half2(__float2half_rn(a), __float2half_rn(b));
    return *reinterpret_cast<uint32_t*>(&h);
}
__device__ __forceinline__ float blockReduceSum(float v) {
    __shared__ float sh[32];
    int lane = threadIdx.x & 31, wid = threadIdx.x >> 5;
    #pragma unroll
    for (int o = 16; o > 0; o >>= 1) v += __shfl_down_sync(0xffffffffu, v, o);
    if (lane == 0) sh[wid] = v;
    __syncthreads();
    int nw = (blockDim.x + 31) >> 5;
    v = (wid == 0 && lane < nw) ? sh[lane] : 0.0f;
    if (wid == 0) {
        #pragma unroll
        for (int o = 16; o > 0; o >>= 1) v += __shfl_down_sync(0xffffffffu, v, o);
    }
    return v;
}
__device__ __forceinline__ float hi_of(float x) {
    return __half2float(__float2half_rn(x));
}

// ---------------- prep kernels -----------------------------------------------
__global__ void zero_kernel() {
    int i = blockIdx.x * blockDim.x + threadIdx.x;
    if (i < KPAD) g_counts[i] = 0.0f;
    if (i < 2)    g_scalars[i] = 0.0f;
    if (i < NMAX) g_best[i] = 0ull;
    int stride = gridDim.x * blockDim.x;
    for (int e = i; e < KPAD * D; e += stride) g_sums[e] = 0.0f;
}
__global__ void halfnorm_kernel(const float* __restrict__ E, int K) {
    int w    = (blockIdx.x * blockDim.x + threadIdx.x) >> 5;
    int lane = threadIdx.x & 31;
    if (w >= KPAD) return;
    if (w >= K) { if (lane == 0) g_halfnorm[w] = INFINITY; return; }
    const float4* row = (const float4*)(E + (size_t)w * D);
    float4 v = row[lane];
    float s = v.x * v.x + v.y * v.y + v.z * v.z + v.w * v.w;
    #pragma unroll
    for (int o = 16; o > 0; o >>= 1) s += __shfl_down_sync(0xffffffffu, s, o);
    if (lane == 0) g_halfnorm[w] = 0.5f * s;
}
// A fragments for m16n8k16: lane holds rows (r, r+8), cols (c0,c0+1,c0+8,c0+9)
__global__ void prep_a(const float* __restrict__ X) {
    int t = blockIdx.x * blockDim.x + threadIdx.x;
    if (t >= (NMAX / 16) * 256) return;
    int lane = t & 31, kc = (t >> 5) & 7, mg = t >> 8;
    int r0 = mg * 16 + (lane >> 2);
    int c0 = kc * 16 + (lane & 3) * 2;
    const float* p0 = X + (size_t)r0 * D + c0;
    const float* p1 = X + (size_t)(r0 + 8) * D + c0;
    float x00 = p0[0], x01 = p0[1], x02 = p0[8], x03 = p0[9];
    float x10 = p1[0], x11 = p1[1], x12 = p1[8], x13 = p1[9];
    float h00 = hi_of(x00), h01 = hi_of(x01), h02 = hi_of(x02), h03 = hi_of(x03);
    float h10 = hi_of(x10), h11 = hi_of(x11), h12 = hi_of(x12), h13 = hi_of(x13);
    uint4 hi, lo;
    hi.x = h2pack(h00, h01); hi.y = h2pack(h10, h11);
    hi.z = h2pack(h02, h03); hi.w = h2pack(h12, h13);
    lo.x = h2pack((x00 - h00) * LO_SCALE, (x01 - h01) * LO_SCALE);
    lo.y = h2pack((x10 - h10) * LO_SCALE, (x11 - h11) * LO_SCALE);
    lo.z = h2pack((x02 - h02) * LO_SCALE, (x03 - h03) * LO_SCALE);
    lo.w = h2pack((x12 - h12) * LO_SCALE, (x13 - h13) * LO_SCALE);
    g_ah4[t] = hi;
    g_al4[t] = lo;
}
// B fragments: lane holds col j = ng*8 + (lane>>2), k rows (k0,k0+1,k0+8,k0+9)
__global__ void prep_b(const float* __restrict__ E, int K) {
    int t = blockIdx.x * blockDim.x + threadIdx.x;
    if (t >= (KPAD / 8) * 256) return;
    int lane = t & 31, kc = (t >> 5) & 7, ng = t >> 8;
    int j = ng * 8 + (lane >> 2);
    int k0 = kc * 16 + (lane & 3) * 2;
    float b0 = 0.f, b1 = 0.f, b2 = 0.f, b3 = 0.f;
    if (j < K) {
        const float* p = E + (size_t)j * D + k0;
        b0 = p[0]; b1 = p[1]; b2 = p[8]; b3 = p[9];
    }
    float g0 = hi_of(b0), g1 = hi_of(b1), g2 = hi_of(b2), g3 = hi_of(b3);
    uint4 v;
    v.x = h2pack(g0, g1);
    v.y = h2pack(g2, g3);
    v.z = h2pack((b0 - g0) * LO_SCALE, (b1 - g1) * LO_SCALE);
    v.w = h2pack((b2 - g2) * LO_SCALE, (b3 - g3) * LO_SCALE);
    g_bf4[t] = v;
}

// ---------------- argmin GEMM (fp16 split, 3-term, m16n8k16) -----------------
// smem: A_hi 32KB | A_lo 32KB | B[2 buf] 32KB each | Hs[2][64]
#define OFF_AL  32768
#define OFF_B   65536
#define OFF_HS  131072
#define SMEM_SZ 131584

__device__ __forceinline__ void issue_tile(uint32_t sb, int buf, int t, int tid) {
    const uint4* src = g_bf4 + (size_t)t * 2048;
    uint32_t dB = sb + OFF_B + buf * 32768;
    #pragma unroll
    for (int i = 0; i < 8; i++) {
        int idx = tid + i * 256;
        cp_async16(dB + idx * 16, src + idx);
    }
    if (tid < 16)
        cp_async16(sb + OFF_HS + buf * 256 + tid * 16, g_halfnorm + t * 64 + tid * 4);
}

__global__ __launch_bounds__(256, 1)
void argmin_mma(int K) {
    extern __shared__ char smem[];
    uint32_t sb = smem_to_u32(smem);
    const int tid   = threadIdx.x;
    const int lane  = tid & 31, wid = tid >> 5;
    const int mwarp = wid >> 1, nwarp = wid & 1;     // 4 x 2
    const int rt  = blockIdx.x >> 2;
    const int seg = blockIdx.x & 3;
    const int tb = (seg * NTILE) / NSEG;
    const int te = ((seg + 1) * NTILE) / NSEG;

    // prologue: A tile (hi+lo) + first two B tiles via cp.async
    {
        const uint4* srcH = g_ah4 + (size_t)rt * 2048;
        const uint4* srcL = g_al4 + (size_t)rt * 2048;
        #pragma unroll
        for (int i = 0; i < 8; i++) {
            int idx = tid + i * 256;
            cp_async16(sb + idx * 16, srcH + idx);
            cp_async16(sb + OFF_AL + idx * 16, srcL + idx);
        }
        issue_tile(sb, 0, tb, tid);
        CP_COMMIT();                        // G0: A + tile tb
        if (tb + 1 < te) issue_tile(sb, 1, tb + 1, tid);
        CP_COMMIT();                        // G1
        CP_WAIT1();                         // G0 done
        __syncthreads();
    }

    const uint4* AsH = (const uint4*)smem;
    const uint4* AsL = (const uint4*)(smem + OFF_AL);

    float best[4]; int bidx[4];
    #pragma unroll
    for (int r = 0; r < 4; r++) { best[r] = -INFINITY; bidx[r] = 0; }

    for (int t = tb; t < te; t++) {
        const int buf = (t - tb) & 1;
        const uint4* Bs = (const uint4*)(smem + OFF_B + buf * 32768);

        float accH[2][4][4], accC[2][4][4];
        #pragma unroll
        for (int mf = 0; mf < 2; mf++)
            #pragma unroll
            for (int nf = 0; nf < 4; nf++)
                #pragma unroll
                for (int e = 0; e < 4; e++) { accH[mf][nf][e] = 0.0f; accC[mf][nf][e] = 0.0f; }

        #pragma unroll
        for (int kc = 0; kc < 8; kc++) {
            uint4 ah[2], al[2];
            #pragma unroll
            for (int mf = 0; mf < 2; mf++) {
                int idx = ((mwarp * 2 + mf) * 8 + kc) * 32 + lane;
                ah[mf] = AsH[idx];
                al[mf] = AsL[idx];
            }
            uint4 bv[4];
            #pragma unroll
            for (int nf = 0; nf < 4; nf++)
                bv[nf] = Bs[((nwarp * 4 + nf) * 8 + kc) * 32 + lane];
            #pragma unroll
            for (int mf = 0; mf < 2; mf++)
                #pragma unroll
                for (int nf = 0; nf < 4; nf++) {
                    MMA16(accH[mf][nf], ah[mf], bv[nf].x, bv[nf].y);
                    MMA16(accC[mf][nf], ah[mf], bv[nf].z, bv[nf].w);
                    MMA16(accC[mf][nf], al[mf], bv[nf].x, bv[nf].y);
                }
        }

        // epilogue: score = hh + cross*2^-12 - halfnorm; running argmax
        const float* Hsf = (const float*)(smem + OFF_HS + buf * 256);
        const int cb = nwarp * 32 + (lane & 3) * 2;
        #pragma unroll
        for (int mf = 0; mf < 2; mf++)
            #pragma unroll
            for (int nf = 0; nf < 4; nf++) {
                int cl = cb + nf * 8;
                float hn0 = Hsf[cl], hn1 = Hsf[cl + 1];
                int j0 = t * 64 + cl;
                float s0 = accH[mf][nf][0] + accC[mf][nf][0] * LO_INV - hn0;
                float s1 = accH[mf][nf][1] + accC[mf][nf][1] * LO_INV - hn1;
                float s2 = accH[mf][nf][2] + accC[mf][nf][2] * LO_INV - hn0;
                float s3 = accH[mf][nf][3] + accC[mf][nf][3] * LO_INV - hn1;
                int r0 = mf * 2, r1 = mf * 2 + 1;
                if (s0 > best[r0]) { best[r0] = s0; bidx[r0] = j0; }
                if (s1 > best[r0]) { best[r0] = s1; bidx[r0] = j0 + 1; }
                if (s2 > best[r1]) { best[r1] = s2; bidx[r1] = j0; }
                if (s3 > best[r1]) { best[r1] = s3; bidx[r1] = j0 + 1; }
            }

        __syncthreads();                       // everyone done reading buf
        if (t + 2 < te) issue_tile(sb, buf, t + 2, tid);
        CP_COMMIT();
        CP_WAIT1();                            // tile t+1 resident
        __syncthreads();
    }

    // merge into global packed (score, ~idx) via atomicMax
    #pragma unroll
    for (int rs = 0; rs < 4; rs++) {
        int mf = rs >> 1, rh = rs & 1;
        int row = rt * 128 + mwarp * 32 + mf * 16 + (lane >> 2) + rh * 8;
        atomicMax(&g_best[row], pack_cand(best[rs], bidx[rs]));
    }
}

__global__ void decode_kernel(int N) {
    int i = blockIdx.x * blockDim.x + threadIdx.x;
    if (i < N) g_bestidx[i] = (int)(~(unsigned int)(g_best[i] & 0xffffffffull));
}

// ---------------- tail kernels (unchanged, known-correct) --------------------
__global__ void scatter_kernel(const float* __restrict__ X, int N) {
    int w    = (blockIdx.x * blockDim.x + threadIdx.x) >> 5;
    int lane = threadIdx.x & 31;
    if (w >= N) return;
    int j = g_bestidx[w];
    float4 v = ((const float4*)(X + (size_t)w * D))[lane];
    float* dst = &g_sums[(size_t)j * D + lane * 4];
    atomicAdd(dst + 0, v.x); atomicAdd(dst + 1, v.y);
    atomicAdd(dst + 2, v.z); atomicAdd(dst + 3, v.w);
    if (lane == 0) atomicAdd(&g_counts[j], 1.0f);
}
__global__ void size_kernel(const float* __restrict__ csize, int K) {
    int j = blockIdx.x * blockDim.x + threadIdx.x;
    float ns = 0.0f;
    if (j < K) {
        ns = csize[j] * 0.99f + g_counts[j] * 0.01f;
        g_counts[j] = ns;
    }
    float tot = blockReduceSum(ns);
    if (threadIdx.x == 0) atomicAdd(&g_scalars[0], tot);
}
__global__ void mean_kernel(const float* __restrict__ csum, int K) {
    int e = blockIdx.x * blockDim.x + threadIdx.x;
    if (e >= K * D) return;
    int j = e >> 7;
    float nsamp = g_scalars[0];
    float smoothed = (g_counts[j] + 1e-5f) * nsamp / (nsamp + (float)K * 1e-5f);
    g_newmean[e] = (csum[e] * 0.99f + g_sums[e] * 0.01f) / smoothed;
}
__global__ void gather_kernel(const float* __restrict__ X, float* __restrict__ out,
                              int N) {
    int e = blockIdx.x * blockDim.x + threadIdx.x;
    int i = e >> 7, d = e & 127;
    int j = g_bestidx[i];
    float q = g_newmean[(size_t)j * D + d];
    float x = X[e];
    out[e] = x + (q - x);
    float df = x - q;
    float tot = blockReduceSum(df * df);
    if (threadIdx.x == 0) atomicAdd(&g_scalars[1], tot);
}
__global__ void final_kernel(float* __restrict__ out, int N, long long out_size) {
    int i = blockIdx.x * blockDim.x + threadIdx.x;
    long long base = (long long)N * D;
    if (i < N && base + i < out_size) out[base + i] = (float)g_bestidx[i];
    if (i == 0 && base + N < out_size)
        out[base + N] = 0.25f * g_scalars[1] / (float)((long long)N * D);
}

// ---------------- launch ------------------------------------------------------
extern "C" void kernel_launch(void* const* d_in, const int* in_sizes, int n_in,
                              void* d_out, int out_size) {
    const float* X     = (const float*)d_in[0];
    const float* E     = (const float*)d_in[1];
    const float* csize = (const float*)d_in[2];
    const float* csum  = (const float*)d_in[3];
    float* out = (float*)d_out;

    int K = in_sizes[2];
    int N = in_sizes[0] / D;

    cudaFuncSetAttribute(argmin_mma, cudaFuncAttributeMaxDynamicSharedMemorySize,
                         SMEM_SZ);

    zero_kernel<<<(KPAD * D + 255) / 256, 256>>>();
    halfnorm_kernel<<<(KPAD * 32 + 255) / 256, 256>>>(E, K);
    prep_a<<<((NMAX / 16) * 256 + 255) / 256, 256>>>(X);
    prep_b<<<((KPAD / 8) * 256 + 255) / 256, 256>>>(E, K);
    argmin_mma<<<(N / 128) * NSEG, 256, SMEM_SZ>>>(K);
    decode_kernel<<<(N + 255) / 256, 256>>>(N);
    scatter_kernel<<<(N * 32 + 255) / 256, 256>>>(X, N);
    size_kernel<<<(K + 255) / 256, 256>>>(csize, K);
    mean_kernel<<<(K * D + 255) / 256, 256>>>(csum, K);
    gather_kernel<<<(N * D) / 256, 256>>>(X, out, N);
    final_kernel<<<(N + 255) / 256, 256>>>(out, N, (long long)out_size);
}

// round 6
// speedup vs baseline: 3.6058x; 1.0565x over previous
#include <cuda_runtime.h>
#include <cuda_fp16.h>
#include <cstdint>
#include <math.h>

#define D       128
#define NMAX    32768
#define KPAD    10112                 // 158 tiles * 64
#define NTILE   (KPAD / 64)           // 158
#define NSEG    4
#define LO_SCALE   4096.0f
#define LO_INV     (1.0f / 4096.0f)

// ---------------- scratch ----------------------------------------------------
__device__ float g_halfnorm[KPAD];
__device__ unsigned long long g_best[NMAX];
__device__ int   g_bestidx[NMAX];
__device__ float g_counts[KPAD];
__device__ float g_sums[KPAD * D];
__device__ float g_newmean[KPAD * D];
__device__ float g_scalars[2];

// fragment-ordered fp16 operands
__device__ __align__(16) uint4 g_ah4[(NMAX / 16) * 8 * 32];   // 8 MB
__device__ __align__(16) uint4 g_al4[(NMAX / 16) * 8 * 32];   // 8 MB
__device__ __align__(16) uint4 g_bf4[(KPAD / 8) * 8 * 32];    // 5.2 MB

// ---------------- helpers ----------------------------------------------------
__device__ __forceinline__ uint32_t smem_to_u32(const void* p) {
    uint32_t a;
    asm("{ .reg .u64 t; cvta.to.shared.u64 t, %1; cvt.u32.u64 %0, t; }"
        : "=r"(a) : "l"(p));
    return a;
}
__device__ __forceinline__ unsigned long long cvta_g(const void* p) {
    unsigned long long r;
    asm("cvta.to.global.u64 %0, %1;" : "=l"(r) : "l"(p));
    return r;
}
__device__ __forceinline__ void cp_async16(uint32_t dst, const void* src) {
    asm volatile("cp.async.cg.shared.global [%0], [%1], 16;"
                 :: "r"(dst), "l"(cvta_g(src)) : "memory");
}
#define CP_COMMIT() asm volatile("cp.async.commit_group;" ::: "memory")
#define CP_WAIT1()  asm volatile("cp.async.wait_group 1;" ::: "memory")
#define GROUP_BAR(g) asm volatile("bar.sync %0, 256;" :: "r"((g) + 1) : "memory")

#define MMA16(d, a, b0, b1) \
    asm volatile("mma.sync.aligned.m16n8k16.row.col.f32.f16.f16.f32 " \
        "{%0,%1,%2,%3},{%4,%5,%6,%7},{%8,%9},{%0,%1,%2,%3};" \
        : "+f"((d)[0]), "+f"((d)[1]), "+f"((d)[2]), "+f"((d)[3]) \
        : "r"((a).x), "r"((a).y), "r"((a).z), "r"((a).w), \
          "r"(b0), "r"(b1))

__device__ __forceinline__ unsigned long long pack_cand(float s, int j) {
    uint32_t u = __float_as_uint(s);
    u = (u & 0x80000000u) ? ~u : (u | 0x80000000u);
    return ((unsigned long long)u << 32) | (uint32_t)(~j);
}
__device__ __forceinline__ uint32_t h2pack(float a, float b) {
    __half2 h = __halves2half2(__float2half_rn(a), __float2half_rn(b));
    return *reinterpret_cast<uint32_t*>(&h);
}
__device__ __forceinline__ float blockReduceSum(float v) {
    __shared__ float sh[32];
    int lane = threadIdx.x & 31, wid = threadIdx.x >> 5;
    #pragma unroll
    for (int o = 16; o > 0; o >>= 1) v += __shfl_down_sync(0xffffffffu, v, o);
    if (lane == 0) sh[wid] = v;
    __syncthreads();
    int nw = (blockDim.x + 31) >> 5;
    v = (wid == 0 && lane < nw) ? sh[lane] : 0.0f;
    if (wid == 0) {
        #pragma unroll
        for (int o = 16; o > 0; o >>= 1) v += __shfl_down_sync(0xffffffffu, v, o);
    }
    return v;
}
__device__ __forceinline__ float hi_of(float x) {
    return __half2float(__float2half_rn(x));
}

// ---------------- prep kernels -----------------------------------------------
__global__ void zero_kernel() {
    int i = blockIdx.x * blockDim.x + threadIdx.x;
    if (i < KPAD) g_counts[i] = 0.0f;
    if (i < 2)    g_scalars[i] = 0.0f;
    if (i < NMAX) g_best[i] = 0ull;
    int stride = gridDim.x * blockDim.x;
    for (int e = i; e < KPAD * D; e += stride) g_sums[e] = 0.0f;
}
__global__ void halfnorm_kernel(const float* __restrict__ E, int K) {
    int w    = (blockIdx.x * blockDim.x + threadIdx.x) >> 5;
    int lane = threadIdx.x & 31;
    if (w >= KPAD) return;
    if (w >= K) { if (lane == 0) g_halfnorm[w] = INFINITY; return; }
    const float4* row = (const float4*)(E + (size_t)w * D);
    float4 v = row[lane];
    float s = v.x * v.x + v.y * v.y + v.z * v.z + v.w * v.w;
    #pragma unroll
    for (int o = 16; o > 0; o >>= 1) s += __shfl_down_sync(0xffffffffu, s, o);
    if (lane == 0) g_halfnorm[w] = 0.5f * s;
}
__global__ void prep_a(const float* __restrict__ X) {
    int t = blockIdx.x * blockDim.x + threadIdx.x;
    if (t >= (NMAX / 16) * 256) return;
    int lane = t & 31, kc = (t >> 5) & 7, mg = t >> 8;
    int r0 = mg * 16 + (lane >> 2);
    int c0 = kc * 16 + (lane & 3) * 2;
    const float* p0 = X + (size_t)r0 * D + c0;
    const float* p1 = X + (size_t)(r0 + 8) * D + c0;
    float x00 = p0[0], x01 = p0[1], x02 = p0[8], x03 = p0[9];
    float x10 = p1[0], x11 = p1[1], x12 = p1[8], x13 = p1[9];
    float h00 = hi_of(x00), h01 = hi_of(x01), h02 = hi_of(x02), h03 = hi_of(x03);
    float h10 = hi_of(x10), h11 = hi_of(x11), h12 = hi_of(x12), h13 = hi_of(x13);
    uint4 hi, lo;
    hi.x = h2pack(h00, h01); hi.y = h2pack(h10, h11);
    hi.z = h2pack(h02, h03); hi.w = h2pack(h12, h13);
    lo.x = h2pack((x00 - h00) * LO_SCALE, (x01 - h01) * LO_SCALE);
    lo.y = h2pack((x10 - h10) * LO_SCALE, (x11 - h11) * LO_SCALE);
    lo.z = h2pack((x02 - h02) * LO_SCALE, (x03 - h03) * LO_SCALE);
    lo.w = h2pack((x12 - h12) * LO_SCALE, (x13 - h13) * LO_SCALE);
    g_ah4[t] = hi;
    g_al4[t] = lo;
}
__global__ void prep_b(const float* __restrict__ E, int K) {
    int t = blockIdx.x * blockDim.x + threadIdx.x;
    if (t >= (KPAD / 8) * 256) return;
    int lane = t & 31, kc = (t >> 5) & 7, ng = t >> 8;
    int j = ng * 8 + (lane >> 2);
    int k0 = kc * 16 + (lane & 3) * 2;
    float b0 = 0.f, b1 = 0.f, b2 = 0.f, b3 = 0.f;
    if (j < K) {
        const float* p = E + (size_t)j * D + k0;
        b0 = p[0]; b1 = p[1]; b2 = p[8]; b3 = p[9];
    }
    float g0 = hi_of(b0), g1 = hi_of(b1), g2 = hi_of(b2), g3 = hi_of(b3);
    uint4 v;
    v.x = h2pack(g0, g1);
    v.y = h2pack(g2, g3);
    v.z = h2pack((b0 - g0) * LO_SCALE, (b1 - g1) * LO_SCALE);
    v.w = h2pack((b2 - g2) * LO_SCALE, (b3 - g3) * LO_SCALE);
    g_bf4[t] = v;
}

// ---------------- argmin GEMM: 512 thr, 2 desynced 8-warp groups -------------
// smem: A_hi 32KB | A_lo 32KB | B[4 slots] 32KB each | Hs[4][64]
#define OFF_AL  32768
#define OFF_B   65536
#define OFF_HS  196608
#define SMEM_SZ 197632

__device__ __forceinline__ void issue_tile(uint32_t sb, int slot, int t, int ltid) {
    const uint4* src = g_bf4 + (size_t)t * 2048;
    uint32_t dB = sb + OFF_B + slot * 32768;
    #pragma unroll
    for (int i = 0; i < 8; i++) {
        int idx = ltid + i * 256;
        cp_async16(dB + idx * 16, src + idx);
    }
    if (ltid < 16)
        cp_async16(sb + OFF_HS + slot * 256 + ltid * 16,
                   g_halfnorm + t * 64 + ltid * 4);
}

__global__ __launch_bounds__(512, 1)
void argmin_mma(int K) {
    extern __shared__ char smem[];
    uint32_t sb = smem_to_u32(smem);
    const int tid   = threadIdx.x;
    const int gid   = tid >> 8;                  // group 0 / 1
    const int ltid  = tid & 255;
    const int lane  = tid & 31;
    const int lwid  = (tid >> 5) & 7;            // warp within group
    const int mwarp = lwid >> 1, nwarp = lwid & 1;
    const int rt  = blockIdx.x >> 2;
    const int seg = blockIdx.x & 3;
    const int tb = (seg * NTILE) / NSEG;
    const int te = ((seg + 1) * NTILE) / NSEG;
    const int t0 = tb + gid;                     // group handles t ≡ gid (mod 2)

    // prologue: A tile (all 512 threads) + each group's first two B tiles
    {
        const uint4* srcH = g_ah4 + (size_t)rt * 2048;
        const uint4* srcL = g_al4 + (size_t)rt * 2048;
        #pragma unroll
        for (int i = 0; i < 4; i++) {
            int idx = tid + i * 512;
            cp_async16(sb + idx * 16, srcH + idx);
            cp_async16(sb + OFF_AL + idx * 16, srcL + idx);
        }
        if (t0 < te) issue_tile(sb, gid * 2, t0, ltid);
        CP_COMMIT();                         // G0: A + first tile
        if (t0 + 2 < te) issue_tile(sb, gid * 2 + 1, t0 + 2, ltid);
        CP_COMMIT();                         // G1
        CP_WAIT1();                          // G0 done (this thread)
        __syncthreads();                     // A + both groups' first tiles visible
    }

    const uint4* AsH = (const uint4*)smem;
    const uint4* AsL = (const uint4*)(smem + OFF_AL);

    float best[4]; int bidx[4];
    #pragma unroll
    for (int r = 0; r < 4; r++) { best[r] = -INFINITY; bidx[r] = 0; }

    int s = 0;
    for (int t = t0; t < te; t += 2, s ^= 1) {
        const int slot = gid * 2 + s;
        const uint4* Bs = (const uint4*)(smem + OFF_B + slot * 32768);

        float accH[2][4][4], accC[2][4][4];
        #pragma unroll
        for (int mf = 0; mf < 2; mf++)
            #pragma unroll
            for (int nf = 0; nf < 4; nf++)
                #pragma unroll
                for (int e = 0; e < 4; e++) { accH[mf][nf][e] = 0.0f; accC[mf][nf][e] = 0.0f; }

        #pragma unroll
        for (int kc = 0; kc < 8; kc++) {
            uint4 ah[2], al[2];
            #pragma unroll
            for (int mf = 0; mf < 2; mf++) {
                int idx = ((mwarp * 2 + mf) * 8 + kc) * 32 + lane;
                ah[mf] = AsH[idx];
                al[mf] = AsL[idx];
            }
            uint4 bv[4];
            #pragma unroll
            for (int nf = 0; nf < 4; nf++)
                bv[nf] = Bs[((nwarp * 4 + nf) * 8 + kc) * 32 + lane];
            #pragma unroll
            for (int mf = 0; mf < 2; mf++)
                #pragma unroll
                for (int nf = 0; nf < 4; nf++) {
                    MMA16(accH[mf][nf], ah[mf], bv[nf].x, bv[nf].y);
                    MMA16(accC[mf][nf], ah[mf], bv[nf].z, bv[nf].w);
                    MMA16(accC[mf][nf], al[mf], bv[nf].x, bv[nf].y);
                }
        }

        // epilogue: score = hh + cross*2^-12 - halfnorm; running argmax
        const float* Hsf = (const float*)(smem + OFF_HS + slot * 256);
        const int cb = nwarp * 32 + (lane & 3) * 2;
        #pragma unroll
        for (int mf = 0; mf < 2; mf++)
            #pragma unroll
            for (int nf = 0; nf < 4; nf++) {
                int cl = cb + nf * 8;
                float hn0 = Hsf[cl], hn1 = Hsf[cl + 1];
                int j0 = t * 64 + cl;
                float s0 = accH[mf][nf][0] + accC[mf][nf][0] * LO_INV - hn0;
                float s1 = accH[mf][nf][1] + accC[mf][nf][1] * LO_INV - hn1;
                float s2 = accH[mf][nf][2] + accC[mf][nf][2] * LO_INV - hn0;
                float s3 = accH[mf][nf][3] + accC[mf][nf][3] * LO_INV - hn1;
                int r0 = mf * 2, r1 = mf * 2 + 1;
                if (s0 > best[r0]) { best[r0] = s0; bidx[r0] = j0; }
                if (s1 > best[r0]) { best[r0] = s1; bidx[r0] = j0 + 1; }
                if (s2 > best[r1]) { best[r1] = s2; bidx[r1] = j0; }
                if (s3 > best[r1]) { best[r1] = s3; bidx[r1] = j0 + 1; }
            }

        GROUP_BAR(gid);                      // this group done reading slot
        if (t + 4 < te) issue_tile(sb, slot, t + 4, ltid);
        CP_COMMIT();
        CP_WAIT1();                          // tile t+2 resident (this thread)
        GROUP_BAR(gid);
    }

    // merge into global packed (score, ~idx) via atomicMax
    #pragma unroll
    for (int rs = 0; rs < 4; rs++) {
        int mf = rs >> 1, rh = rs & 1;
        int row = rt * 128 + mwarp * 32 + mf * 16 + (lane >> 2) + rh * 8;
        atomicMax(&g_best[row], pack_cand(best[rs], bidx[rs]));
    }
}

// ---------------- tail kernels -----------------------------------------------
__global__ void scatter_kernel(const float* __restrict__ X, int N) {
    int w    = (blockIdx.x * blockDim.x + threadIdx.x) >> 5;
    int lane = threadIdx.x & 31;
    if (w >= N) return;
    int j = (int)(~(unsigned int)(g_best[w] & 0xffffffffull));   // fused decode
    if (lane == 0) g_bestidx[w] = j;
    float4 v = ((const float4*)(X + (size_t)w * D))[lane];
    float* dst = &g_sums[(size_t)j * D + lane * 4];
    atomicAdd(dst + 0, v.x); atomicAdd(dst + 1, v.y);
    atomicAdd(dst + 2, v.z); atomicAdd(dst + 3, v.w);
    if (lane == 0) atomicAdd(&g_counts[j], 1.0f);
}
__global__ void size_kernel(const float* __restrict__ csize, int K) {
    int j = blockIdx.x * blockDim.x + threadIdx.x;
    float ns = 0.0f;
    if (j < K) {
        ns = csize[j] * 0.99f + g_counts[j] * 0.01f;
        g_counts[j] = ns;
    }
    float tot = blockReduceSum(ns);
    if (threadIdx.x == 0) atomicAdd(&g_scalars[0], tot);
}
__global__ void mean_kernel(const float* __restrict__ csum, int K) {
    int e = blockIdx.x * blockDim.x + threadIdx.x;
    if (e >= K * D) return;
    int j = e >> 7;
    float nsamp = g_scalars[0];
    float smoothed = (g_counts[j] + 1e-5f) * nsamp / (nsamp + (float)K * 1e-5f);
    g_newmean[e] = (csum[e] * 0.99f + g_sums[e] * 0.01f) / smoothed;
}
__global__ void gather_kernel(const float* __restrict__ X, float* __restrict__ out,
                              int N) {
    int e = blockIdx.x * blockDim.x + threadIdx.x;
    int i = e >> 7, d = e & 127;
    int j = g_bestidx[i];
    float q = g_newmean[(size_t)j * D + d];
    float x = X[e];
    out[e] = x + (q - x);
    float df = x - q;
    float tot = blockReduceSum(df * df);
    if (threadIdx.x == 0) atomicAdd(&g_scalars[1], tot);
}
__global__ void final_kernel(float* __restrict__ out, int N, long long out_size) {
    int i = blockIdx.x * blockDim.x + threadIdx.x;
    long long base = (long long)N * D;
    if (i < N && base + i < out_size) out[base + i] = (float)g_bestidx[i];
    if (i == 0 && base + N < out_size)
        out[base + N] = 0.25f * g_scalars[1] / (float)((long long)N * D);
}

// ---------------- launch ------------------------------------------------------
extern "C" void kernel_launch(void* const* d_in, const int* in_sizes, int n_in,
                              void* d_out, int out_size) {
    const float* X     = (const float*)d_in[0];
    const float* E     = (const float*)d_in[1];
    const float* csize = (const float*)d_in[2];
    const float* csum  = (const float*)d_in[3];
    float* out = (float*)d_out;

    int K = in_sizes[2];
    int N = in_sizes[0] / D;

    cudaFuncSetAttribute(argmin_mma, cudaFuncAttributeMaxDynamicSharedMemorySize,
                         SMEM_SZ);

    zero_kernel<<<(KPAD * D + 255) / 256, 256>>>();
    halfnorm_kernel<<<(KPAD * 32 + 255) / 256, 256>>>(E, K);
    prep_a<<<((NMAX / 16) * 256 + 255) / 256, 256>>>(X);
    prep_b<<<((KPAD / 8) * 256 + 255) / 256, 256>>>(E, K);
    argmin_mma<<<(N / 128) * NSEG, 512, SMEM_SZ>>>(K);
    scatter_kernel<<<(N * 32 + 255) / 256, 256>>>(X, N);
    size_kernel<<<(K + 255) / 256, 256>>>(csize, K);
    mean_kernel<<<(K * D + 255) / 256, 256>>>(csum, K);
    gather_kernel<<<(N * D) / 256, 256>>>(X, out, N);
    final_kernel<<<(N + 255) / 256, 256>>>(out, N, (long long)out_size);
}